// round 1
// baseline (speedup 1.0000x reference)
#include <cuda_runtime.h>
#include <math.h>

#define B_SZ   4
#define SEQ    1024
#define DM     1024
#define NH     16
#define DH     64
#define DFF    2048
#define ROWS   (B_SZ*SEQ)        // 4096
#define LN_EPS 1e-5f

// ---------------- scratch (device globals; no allocation allowed) ----------------
__device__ float g_q[B_SZ*NH*SEQ*DH];     // [B,H,S,64]
__device__ float g_k[B_SZ*NH*SEQ*DH];
__device__ float g_v[B_SZ*NH*SEQ*DH];
__device__ float g_attn[ROWS*DM];         // concat heads [B*S, D]
__device__ float g_tmp[ROWS*DM];          // residual sums
__device__ float g_h[ROWS*DM];            // LN1 output
__device__ float g_ff[ROWS*DFF];          // FF1 output

// =================================================================================
// Fused QKV GEMM: X[4096,1024] @ {wq,wk,wv}[16 heads of 1024x64] -> g_q/g_k/g_v
// 128x128x8 tiles, 256 threads, 8x8 microtile, register prefetch.
// Virtual B matrix has 3072 cols: col c -> tensor t=c/1024, head h=(c%1024)/64, kk=c%64
// =================================================================================
__global__ void __launch_bounds__(256) qkv_gemm_k(
    const float* __restrict__ x,
    const float* __restrict__ wq, const float* __restrict__ wk, const float* __restrict__ wv,
    const float* __restrict__ bq, const float* __restrict__ bk, const float* __restrict__ bv)
{
    __shared__ float As[8][128];
    __shared__ float Bs[8][128];

    const int tid = threadIdx.x;
    const int bm = blockIdx.y * 128;
    const int bn = blockIdx.x * 128;

    // A loader: float4 per thread
    const int a_row = tid >> 1;
    const int a_col = (tid & 1) * 4;
    const float* Aptr = x + (size_t)(bm + a_row) * 1024 + a_col;

    // B loader: thread owns a fixed column group (same head for all 4 cols)
    const int b_row = tid >> 5;          // 0..7
    const int b_col = (tid & 31) * 4;    // 0..124
    const int c0 = bn + b_col;
    const int t_sel = c0 >> 10;
    const int rem   = c0 & 1023;
    const int bh    = rem >> 6;
    const int bkk   = rem & 63;
    const float* w = (t_sel == 0) ? wq : (t_sel == 1) ? wk : wv;
    const float* Bptr = w + ((size_t)bh * 1024 + b_row) * 64 + bkk;   // + k0*64 per step

    float acc[8][8];
    #pragma unroll
    for (int i = 0; i < 8; i++)
        #pragma unroll
        for (int j = 0; j < 8; j++) acc[i][j] = 0.f;

    const int ty = tid >> 4, tx = tid & 15;

    float4 av = *(const float4*)(Aptr);
    float4 bv4 = *(const float4*)(Bptr);

    for (int k0 = 0; k0 < 1024; k0 += 8) {
        As[a_col + 0][a_row] = av.x;
        As[a_col + 1][a_row] = av.y;
        As[a_col + 2][a_row] = av.z;
        As[a_col + 3][a_row] = av.w;
        *(float4*)&Bs[b_row][b_col] = bv4;
        __syncthreads();

        if (k0 + 8 < 1024) {
            av  = *(const float4*)(Aptr + k0 + 8);
            bv4 = *(const float4*)(Bptr + (size_t)(k0 + 8) * 64);
        }

        #pragma unroll
        for (int kk = 0; kk < 8; kk++) {
            float af[8], bf[8];
            *(float4*)&af[0] = *(float4*)&As[kk][ty * 8];
            *(float4*)&af[4] = *(float4*)&As[kk][ty * 8 + 4];
            *(float4*)&bf[0] = *(float4*)&Bs[kk][tx * 8];
            *(float4*)&bf[4] = *(float4*)&Bs[kk][tx * 8 + 4];
            #pragma unroll
            for (int i = 0; i < 8; i++)
                #pragma unroll
                for (int j = 0; j < 8; j++)
                    acc[i][j] = fmaf(af[i], bf[j], acc[i][j]);
        }
        __syncthreads();
    }

    // scatter: cols cbase..cbase+7 never cross a head boundary (cbase%64 <= 56)
    const int cbase = bn + tx * 8;
    const int ot = cbase >> 10;
    const int orem = cbase & 1023;
    const int oh = orem >> 6;
    const int okk = orem & 63;
    float* outp = (ot == 0) ? g_q : (ot == 1) ? g_k : g_v;
    const float* biasp = ((ot == 0) ? bq : (ot == 1) ? bk : bv) + oh * 64 + okk;

    #pragma unroll
    for (int i = 0; i < 8; i++) {
        const int r = bm + ty * 8 + i;
        const int bb = r >> 10, srow = r & 1023;
        float* op = outp + (((size_t)(bb * 16 + oh)) << 16) + (srow << 6) + okk;
        #pragma unroll
        for (int j = 0; j < 8; j++)
            op[j] = acc[i][j] + biasp[j];
    }
}

// =================================================================================
// Attention: 1 thread = 1 query row (private online softmax), KV staged 16 rows at
// a time in smem (broadcast reads). grid = (S/128, B*H), 128 threads.
// =================================================================================
__global__ void __launch_bounds__(128) attn_k()
{
    const int tid = threadIdx.x;
    const int bhid = blockIdx.y;
    const int row = blockIdx.x * 128 + tid;       // query position s

    const float* Qp = g_q + ((size_t)bhid << 16) + (row << 6);
    const float* Kp = g_k + ((size_t)bhid << 16);
    const float* Vp = g_v + ((size_t)bhid << 16);

    float q[64];
    #pragma unroll
    for (int d = 0; d < 64; d += 4) {
        float4 t = *(const float4*)(Qp + d);
        q[d] = t.x * 0.125f; q[d+1] = t.y * 0.125f; q[d+2] = t.z * 0.125f; q[d+3] = t.w * 0.125f;
    }
    float o[64];
    #pragma unroll
    for (int d = 0; d < 64; d++) o[d] = 0.f;
    float m = -1e30f, l = 0.f;

    __shared__ float Ks[16][64];
    __shared__ float Vs[16][64];

    for (int j0 = 0; j0 < SEQ; j0 += 16) {
        __syncthreads();
        #pragma unroll
        for (int u = 0; u < 2; u++) {
            const int id4 = tid + u * 128;        // 0..255 float4 slots
            const int r = id4 >> 4;
            const int c = (id4 & 15) * 4;
            *(float4*)&Ks[r][c] = *(const float4*)(Kp + ((j0 + r) << 6) + c);
            *(float4*)&Vs[r][c] = *(const float4*)(Vp + ((j0 + r) << 6) + c);
        }
        __syncthreads();

        float s[16];
        #pragma unroll
        for (int jj = 0; jj < 16; jj++) s[jj] = 0.f;
        #pragma unroll
        for (int d = 0; d < 64; d += 4) {
            const float q0 = q[d], q1 = q[d+1], q2 = q[d+2], q3 = q[d+3];
            #pragma unroll
            for (int jj = 0; jj < 16; jj++) {
                float4 kv = *(float4*)&Ks[jj][d];
                s[jj] = fmaf(q0, kv.x, fmaf(q1, kv.y, fmaf(q2, kv.z, fmaf(q3, kv.w, s[jj]))));
            }
        }

        float mt = s[0];
        #pragma unroll
        for (int jj = 1; jj < 16; jj++) mt = fmaxf(mt, s[jj]);
        if (mt > m) {
            const float sc = __expf(m - mt);
            #pragma unroll
            for (int d = 0; d < 64; d++) o[d] *= sc;
            l *= sc;
            m = mt;
        }
        #pragma unroll
        for (int jj = 0; jj < 16; jj++) {
            const float p = __expf(s[jj] - m);
            l += p;
            #pragma unroll
            for (int d = 0; d < 64; d += 4) {
                float4 vv = *(float4*)&Vs[jj][d];
                o[d]   = fmaf(p, vv.x, o[d]);
                o[d+1] = fmaf(p, vv.y, o[d+1]);
                o[d+2] = fmaf(p, vv.z, o[d+2]);
                o[d+3] = fmaf(p, vv.w, o[d+3]);
            }
        }
    }

    const float inv = 1.f / l;
    const int bb = bhid >> 4, hh = bhid & 15;
    float* op = g_attn + ((size_t)(bb * 1024 + row)) * 1024 + hh * 64;
    #pragma unroll
    for (int d = 0; d < 64; d += 4) {
        float4 ov;
        ov.x = o[d] * inv; ov.y = o[d+1] * inv; ov.z = o[d+2] * inv; ov.w = o[d+3] * inv;
        *(float4*)(op + d) = ov;
    }
}

// =================================================================================
// Generic SGEMM: C[M,N] = A[M,K] @ B[K,N] + bias[N] (+ res[M,N]) (optional ReLU)
// 128x128x8 tiles, 256 threads, 8x8 microtile, register prefetch.
// Shapes here are all multiples of 128/8 -> no bounds checks.
// =================================================================================
__global__ void __launch_bounds__(256) sgemm_k(
    const float* __restrict__ A, const float* __restrict__ B,
    const float* __restrict__ bias, const float* __restrict__ res,
    float* __restrict__ C, int M, int N, int K, int relu)
{
    __shared__ float As[8][128];
    __shared__ float Bs[8][128];

    const int tid = threadIdx.x;
    const int bm = blockIdx.y * 128;
    const int bn = blockIdx.x * 128;

    const int a_row = tid >> 1;
    const int a_col = (tid & 1) * 4;
    const float* Aptr = A + (size_t)(bm + a_row) * K + a_col;

    const int b_row = tid >> 5;
    const int b_col = (tid & 31) * 4;
    const float* Bptr = B + (size_t)b_row * N + bn + b_col;

    float acc[8][8];
    #pragma unroll
    for (int i = 0; i < 8; i++)
        #pragma unroll
        for (int j = 0; j < 8; j++) acc[i][j] = 0.f;

    const int ty = tid >> 4, tx = tid & 15;

    float4 av = *(const float4*)(Aptr);
    float4 bv4 = *(const float4*)(Bptr);

    for (int k0 = 0; k0 < K; k0 += 8) {
        As[a_col + 0][a_row] = av.x;
        As[a_col + 1][a_row] = av.y;
        As[a_col + 2][a_row] = av.z;
        As[a_col + 3][a_row] = av.w;
        *(float4*)&Bs[b_row][b_col] = bv4;
        __syncthreads();

        if (k0 + 8 < K) {
            av  = *(const float4*)(Aptr + k0 + 8);
            bv4 = *(const float4*)(Bptr + (size_t)(k0 + 8) * N);
        }

        #pragma unroll
        for (int kk = 0; kk < 8; kk++) {
            float af[8], bf[8];
            *(float4*)&af[0] = *(float4*)&As[kk][ty * 8];
            *(float4*)&af[4] = *(float4*)&As[kk][ty * 8 + 4];
            *(float4*)&bf[0] = *(float4*)&Bs[kk][tx * 8];
            *(float4*)&bf[4] = *(float4*)&Bs[kk][tx * 8 + 4];
            #pragma unroll
            for (int i = 0; i < 8; i++)
                #pragma unroll
                for (int j = 0; j < 8; j++)
                    acc[i][j] = fmaf(af[i], bf[j], acc[i][j]);
        }
        __syncthreads();
    }

    #pragma unroll
    for (int i = 0; i < 8; i++) {
        const int r = bm + ty * 8 + i;
        float* cp = C + (size_t)r * N + bn + tx * 8;
        const float* rp = res ? (res + (size_t)r * N + bn + tx * 8) : nullptr;
        #pragma unroll
        for (int j = 0; j < 8; j++) {
            float v = acc[i][j] + bias[bn + tx * 8 + j];
            if (rp) v += rp[j];
            if (relu) v = fmaxf(v, 0.f);
            cp[j] = v;
        }
    }
}

// =================================================================================
// LayerNorm (two-pass, matches ref: gamma*(x-mean)/(std+eps)+beta, std=sqrt(E[(x-m)^2]))
// 1 block per row, 256 threads, 4 elements/thread.
// =================================================================================
__global__ void __launch_bounds__(256) layernorm_k(
    const float* __restrict__ in, const float* __restrict__ gamma,
    const float* __restrict__ beta, float* __restrict__ out)
{
    __shared__ float red[256];
    const int row = blockIdx.x;
    const int tid = threadIdx.x;

    const float4 v = ((const float4*)(in + (size_t)row * 1024))[tid];
    float s = v.x + v.y + v.z + v.w;
    red[tid] = s;
    __syncthreads();
    #pragma unroll
    for (int off = 128; off > 0; off >>= 1) {
        if (tid < off) red[tid] += red[tid + off];
        __syncthreads();
    }
    const float mean = red[0] * (1.f / 1024.f);
    __syncthreads();

    const float d0 = v.x - mean, d1 = v.y - mean, d2 = v.z - mean, d3 = v.w - mean;
    s = d0 * d0 + d1 * d1 + d2 * d2 + d3 * d3;
    red[tid] = s;
    __syncthreads();
    #pragma unroll
    for (int off = 128; off > 0; off >>= 1) {
        if (tid < off) red[tid] += red[tid + off];
        __syncthreads();
    }
    const float var = red[0] * (1.f / 1024.f);
    const float inv = 1.f / (sqrtf(var) + LN_EPS);

    const float4 gv = ((const float4*)gamma)[tid];
    const float4 bv = ((const float4*)beta)[tid];
    float4 ov;
    ov.x = gv.x * d0 * inv + bv.x;
    ov.y = gv.y * d1 * inv + bv.y;
    ov.z = gv.z * d2 * inv + bv.z;
    ov.w = gv.w * d3 * inv + bv.w;
    ((float4*)(out + (size_t)row * 1024))[tid] = ov;
}

// =================================================================================
// Launch
// =================================================================================
static float* sym_addr(const void* symbol)
{
    void* p = nullptr;
    cudaGetSymbolAddress(&p, symbol);
    return (float*)p;
}

extern "C" void kernel_launch(void* const* d_in, const int* in_sizes, int n_in,
                              void* d_out, int out_size)
{
    const float* x     = (const float*)d_in[0];
    const float* wq    = (const float*)d_in[1];
    const float* bq    = (const float*)d_in[2];
    const float* wk    = (const float*)d_in[3];
    const float* bk    = (const float*)d_in[4];
    const float* wv    = (const float*)d_in[5];
    const float* bv    = (const float*)d_in[6];
    const float* wo_w  = (const float*)d_in[7];
    const float* wo_b  = (const float*)d_in[8];
    const float* g1    = (const float*)d_in[9];
    const float* b1    = (const float*)d_in[10];
    const float* ff1_w = (const float*)d_in[11];
    const float* ff1_b = (const float*)d_in[12];
    const float* ff2_w = (const float*)d_in[13];
    const float* ff2_b = (const float*)d_in[14];
    const float* g2    = (const float*)d_in[15];
    const float* b2    = (const float*)d_in[16];

    float* attn = sym_addr(g_attn);
    float* tmp  = sym_addr(g_tmp);
    float* h    = sym_addr(g_h);
    float* ff   = sym_addr(g_ff);

    // 1) QKV projections
    qkv_gemm_k<<<dim3(24, 32), 256>>>(x, wq, wk, wv, bq, bk, bv);

    // 2) attention
    attn_k<<<dim3(SEQ / 128, B_SZ * NH), 128>>>();

    // 3) output projection + residual(x)
    sgemm_k<<<dim3(8, 32), 256>>>(attn, wo_w, wo_b, x, tmp, ROWS, DM, DM, 0);

    // 4) LayerNorm 1
    layernorm_k<<<ROWS, 256>>>(tmp, g1, b1, h);

    // 5) FF1 + ReLU
    sgemm_k<<<dim3(16, 32), 256>>>(h, ff1_w, ff1_b, nullptr, ff, ROWS, DFF, DM, 1);

    // 6) FF2 + residual(h)
    sgemm_k<<<dim3(8, 32), 256>>>(ff, ff2_w, ff2_b, h, tmp, ROWS, DM, DFF, 0);

    // 7) LayerNorm 2 -> output
    layernorm_k<<<ROWS, 256>>>(tmp, g2, b2, (float*)d_out);
}

// round 4
// speedup vs baseline: 1.6666x; 1.6666x over previous
#include <cuda_runtime.h>
#include <cuda_bf16.h>
#include <math.h>
#include <cstdint>

#define B_SZ   4
#define SEQ    1024
#define DM     1024
#define NH     16
#define DFF    2048
#define ROWS   (B_SZ*SEQ)        // 4096
#define LN_EPS 1e-5f

// smem tile geometry (per buffer): 4 bf16 tiles, 128 rows x 40 bf16 (80B stride)
#define ROWB      80
#define TILE_B    (128*ROWB)     // 10240
#define OFF_AHI   0
#define OFF_ALO   (TILE_B)
#define OFF_BHI   (2*TILE_B)
#define OFF_BLO   (3*TILE_B)
#define BUF_B     (4*TILE_B)     // 40960
#define SMEM_TOT  (2*BUF_B)      // 81920

// ---------------- scratch (device globals; no allocation allowed) ----------------
__device__ float g_qkv[ROWS*3*DM];        // [B*S, 3072]
__device__ float g_attn[ROWS*DM];
__device__ float g_tmp[ROWS*DM];
__device__ float g_h[ROWS*DM];
__device__ float g_ff[ROWS*DFF];
__device__ float g_wqkv[DM*3*DM];
__device__ float g_bqkv[3*DM];

// =================================================================================
// helpers
// =================================================================================
__device__ __forceinline__ uint32_t smem_u32(const void* p) {
    uint32_t a;
    asm("{ .reg .u64 t; cvta.to.shared.u64 t, %1; cvt.u32.u64 %0, t; }" : "=r"(a) : "l"(p));
    return a;
}

__device__ __forceinline__ void ldsm4(uint32_t* r, uint32_t addr) {
    asm volatile("ldmatrix.sync.aligned.m8n8.x4.shared.b16 {%0,%1,%2,%3}, [%4];"
                 : "=r"(r[0]), "=r"(r[1]), "=r"(r[2]), "=r"(r[3]) : "r"(addr));
}

__device__ __forceinline__ void mma_bf16(float* d, const uint32_t* a, uint32_t b0, uint32_t b1) {
    asm volatile("mma.sync.aligned.m16n8k16.row.col.f32.bf16.bf16.f32 "
                 "{%0,%1,%2,%3}, {%4,%5,%6,%7}, {%8,%9}, {%0,%1,%2,%3};"
                 : "+f"(d[0]), "+f"(d[1]), "+f"(d[2]), "+f"(d[3])
                 : "r"(a[0]), "r"(a[1]), "r"(a[2]), "r"(a[3]), "r"(b0), "r"(b1));
}

// split fp32 pair into (hi,lo) bf16x2 words
__device__ __forceinline__ void split2(float a, float b, uint32_t& hi, uint32_t& lo) {
    __nv_bfloat16 ah = __float2bfloat16(a);
    __nv_bfloat16 bh = __float2bfloat16(b);
    __nv_bfloat16 al = __float2bfloat16(a - __bfloat162float(ah));
    __nv_bfloat16 bl = __float2bfloat16(b - __bfloat162float(bh));
    __nv_bfloat162 h2; h2.x = ah; h2.y = bh;
    __nv_bfloat162 l2; l2.x = al; l2.y = bl;
    hi = *reinterpret_cast<uint32_t*>(&h2);
    lo = *reinterpret_cast<uint32_t*>(&l2);
}

// =================================================================================
// Pack QKV weights into [1024 K, 3072 N] and bias into [3072]
// =================================================================================
__global__ void __launch_bounds__(256) pack_qkv_k(
    const float* __restrict__ wq, const float* __restrict__ wk, const float* __restrict__ wv,
    const float* __restrict__ bq, const float* __restrict__ bk, const float* __restrict__ bv)
{
    const int idx = blockIdx.x * 256 + threadIdx.x;
    const int n = idx % 3072;
    const int k = idx / 3072;
    const int t = n >> 10;
    const int rem = n & 1023;
    const float* w = (t == 0) ? wq : (t == 1) ? wk : wv;
    g_wqkv[idx] = w[(((rem >> 6) << 10) + k) * 64 + (rem & 63)];
    if (idx < 3072) {
        const float* bp = (t == 0) ? bq : (t == 1) ? bk : bv;
        g_bqkv[idx] = bp[rem];
    }
}

// =================================================================================
// mma.sync bf16x2-split GEMM: C = A@B + bias (+res) (relu opt)
// A[M,K], B[K,N] fp32 row-major. 128x128 CTA tile, K chunks of 32, 256 threads,
// warp tile 32x64, double-buffered smem, software pipeline.
// =================================================================================
__global__ void __launch_bounds__(256) gemm_mma(
    const float* __restrict__ A, const float* __restrict__ Bm,
    const float* __restrict__ bias, const float* __restrict__ res,
    float* __restrict__ C, int M, int N, int K, int relu)
{
    extern __shared__ __align__(128) char sm[];
    const uint32_t sbase = smem_u32(sm);

    const int tid  = threadIdx.x;
    const int wid  = tid >> 5;
    const int lane = tid & 31;
    const int bm = blockIdx.y * 128;
    const int bn = blockIdx.x * 128;
    const int warp_m = wid & 3;
    const int warp_n = wid >> 2;

    // loader mapping
    const int ar  = tid >> 1;            // A row 0..127
    const int ak  = (tid & 1) * 16;      // A k base within chunk
    const int bnl = tid & 127;           // B n within tile
    const int bkl = (tid >> 7) * 16;     // B k base within chunk

    const float* Ap = A + (size_t)(bm + ar) * K + ak;
    const float* Bp = Bm + (size_t)bkl * N + bn + bnl;

    float acc[2][8][4];
    #pragma unroll
    for (int i = 0; i < 2; i++)
        #pragma unroll
        for (int j = 0; j < 8; j++)
            #pragma unroll
            for (int q = 0; q < 4; q++) acc[i][j][q] = 0.f;

    float a_pre[16], b_pre[16];
    const int NCH = K >> 5;

    // ---- prologue: LDG chunk 0 ----
    #pragma unroll
    for (int i = 0; i < 4; i++)
        *(float4*)&a_pre[4 * i] = *(const float4*)(Ap + 4 * i);
    #pragma unroll
    for (int i = 0; i < 16; i++)
        b_pre[i] = Bp[(size_t)i * N];

    for (int c = 0; c < NCH; c++) {
        const uint32_t buf = sbase + (uint32_t)(c & 1) * BUF_B;
        char* bufc = sm + (c & 1) * BUF_B;

        // ---- STS chunk c (split fp32 -> bf16 hi/lo) ----
        #pragma unroll
        for (int i = 0; i < 4; i++) {
            uint32_t h01, l01, h23, l23;
            split2(a_pre[4 * i],     a_pre[4 * i + 1], h01, l01);
            split2(a_pre[4 * i + 2], a_pre[4 * i + 3], h23, l23);
            const uint32_t off = (uint32_t)(ar * ROWB + (ak + 4 * i) * 2);
            *(uint2*)(bufc + OFF_AHI + off) = make_uint2(h01, h23);
            *(uint2*)(bufc + OFF_ALO + off) = make_uint2(l01, l23);
        }
        #pragma unroll
        for (int g = 0; g < 4; g++) {
            uint32_t h01, l01, h23, l23;
            split2(b_pre[4 * g],     b_pre[4 * g + 1], h01, l01);
            split2(b_pre[4 * g + 2], b_pre[4 * g + 3], h23, l23);
            const uint32_t off = (uint32_t)(bnl * ROWB + (bkl + 4 * g) * 2);
            *(uint2*)(bufc + OFF_BHI + off) = make_uint2(h01, h23);
            *(uint2*)(bufc + OFF_BLO + off) = make_uint2(l01, l23);
        }
        __syncthreads();

        // ---- LDG chunk c+1 (in flight during compute) ----
        if (c + 1 < NCH) {
            const int k0 = (c + 1) * 32;
            #pragma unroll
            for (int i = 0; i < 4; i++)
                *(float4*)&a_pre[4 * i] = *(const float4*)(Ap + k0 + 4 * i);
            #pragma unroll
            for (int i = 0; i < 16; i++)
                b_pre[i] = Bp[(size_t)(k0 + i) * N];
        }

        // ---- compute chunk c ----
        #pragma unroll
        for (int ks = 0; ks < 2; ks++) {
            uint32_t a_hi[2][4], a_lo[2][4];
            {
                const int arow = warp_m * 32 + (lane & 15);
                const int acol = ks * 16 + (lane >> 4) * 8;
                #pragma unroll
                for (int im = 0; im < 2; im++) {
                    const uint32_t ad = buf + (uint32_t)((arow + im * 16) * ROWB + acol * 2);
                    ldsm4(a_hi[im], ad + OFF_AHI);
                    ldsm4(a_lo[im], ad + OFF_ALO);
                }
            }
            uint32_t b_hi[4][4], b_lo[4][4];
            {
                const int nrow = warp_n * 64 + ((lane >> 4) << 3) + (lane & 7);
                const int bcol = ks * 16 + ((lane >> 3) & 1) * 8;
                #pragma unroll
                for (int jb = 0; jb < 4; jb++) {
                    const uint32_t bd = buf + (uint32_t)((nrow + jb * 16) * ROWB + bcol * 2);
                    ldsm4(b_hi[jb], bd + OFF_BHI);
                    ldsm4(b_lo[jb], bd + OFF_BLO);
                }
            }
            #pragma unroll
            for (int im = 0; im < 2; im++)
                #pragma unroll
                for (int jn = 0; jn < 8; jn++) {
                    const int jb = jn >> 1;
                    const int sl = (jn & 1) * 2;
                    mma_bf16(acc[im][jn], a_hi[im], b_hi[jb][sl], b_hi[jb][sl + 1]);
                    mma_bf16(acc[im][jn], a_hi[im], b_lo[jb][sl], b_lo[jb][sl + 1]);
                    mma_bf16(acc[im][jn], a_lo[im], b_hi[jb][sl], b_hi[jb][sl + 1]);
                }
        }
    }

    // ---- epilogue ----
    const int row0 = bm + warp_m * 32 + (lane >> 2);
    const int col0 = bn + warp_n * 64 + (lane & 3) * 2;
    #pragma unroll
    for (int im = 0; im < 2; im++) {
        #pragma unroll
        for (int half = 0; half < 2; half++) {      // c0c1 (row) / c2c3 (row+8)
            const int r = row0 + im * 16 + half * 8;
            float* cp = C + (size_t)r * N;
            const float* rp = res ? res + (size_t)r * N : nullptr;
            #pragma unroll
            for (int jn = 0; jn < 8; jn++) {
                const int cc = col0 + jn * 8;
                float2 o;
                o.x = acc[im][jn][2 * half]     + bias[cc];
                o.y = acc[im][jn][2 * half + 1] + bias[cc + 1];
                if (rp) {
                    const float2 rv = *(const float2*)(rp + cc);
                    o.x += rv.x; o.y += rv.y;
                }
                if (relu) { o.x = fmaxf(o.x, 0.f); o.y = fmaxf(o.y, 0.f); }
                *(float2*)(cp + cc) = o;
            }
        }
    }
}

// =================================================================================
// Attention: 1 thread = 1 query row, flash-style, reads g_qkv [B*S, 3072]
// =================================================================================
__global__ void __launch_bounds__(128) attn_k()
{
    const int tid = threadIdx.x;
    const int bhid = blockIdx.y;
    const int row = blockIdx.x * 128 + tid;
    const int bb = bhid >> 4, hh = bhid & 15;

    const float* base = g_qkv + (size_t)(bb * 1024) * 3072;
    const float* Qp = base + (size_t)row * 3072 + hh * 64;
    const float* Kp = base + 1024 + hh * 64;
    const float* Vp = base + 2048 + hh * 64;

    float q[64];
    #pragma unroll
    for (int d = 0; d < 64; d += 4) {
        float4 t = *(const float4*)(Qp + d);
        q[d] = t.x * 0.125f; q[d+1] = t.y * 0.125f; q[d+2] = t.z * 0.125f; q[d+3] = t.w * 0.125f;
    }
    float o[64];
    #pragma unroll
    for (int d = 0; d < 64; d++) o[d] = 0.f;
    float m = -1e30f, l = 0.f;

    __shared__ float Ks[16][64];
    __shared__ float Vs[16][64];

    for (int j0 = 0; j0 < SEQ; j0 += 16) {
        __syncthreads();
        #pragma unroll
        for (int u = 0; u < 2; u++) {
            const int id4 = tid + u * 128;
            const int r = id4 >> 4;
            const int c = (id4 & 15) * 4;
            *(float4*)&Ks[r][c] = *(const float4*)(Kp + (size_t)(j0 + r) * 3072 + c);
            *(float4*)&Vs[r][c] = *(const float4*)(Vp + (size_t)(j0 + r) * 3072 + c);
        }
        __syncthreads();

        float s[16];
        #pragma unroll
        for (int jj = 0; jj < 16; jj++) s[jj] = 0.f;
        #pragma unroll
        for (int d = 0; d < 64; d += 4) {
            const float q0 = q[d], q1 = q[d+1], q2 = q[d+2], q3 = q[d+3];
            #pragma unroll
            for (int jj = 0; jj < 16; jj++) {
                float4 kv = *(float4*)&Ks[jj][d];
                s[jj] = fmaf(q0, kv.x, fmaf(q1, kv.y, fmaf(q2, kv.z, fmaf(q3, kv.w, s[jj]))));
            }
        }

        float mt = s[0];
        #pragma unroll
        for (int jj = 1; jj < 16; jj++) mt = fmaxf(mt, s[jj]);
        if (mt > m) {
            const float sc = __expf(m - mt);
            #pragma unroll
            for (int d = 0; d < 64; d++) o[d] *= sc;
            l *= sc;
            m = mt;
        }
        #pragma unroll
        for (int jj = 0; jj < 16; jj++) {
            const float p = __expf(s[jj] - m);
            l += p;
            #pragma unroll
            for (int d = 0; d < 64; d += 4) {
                float4 vv = *(float4*)&Vs[jj][d];
                o[d]   = fmaf(p, vv.x, o[d]);
                o[d+1] = fmaf(p, vv.y, o[d+1]);
                o[d+2] = fmaf(p, vv.z, o[d+2]);
                o[d+3] = fmaf(p, vv.w, o[d+3]);
            }
        }
    }

    const float inv = 1.f / l;
    float* op = g_attn + ((size_t)(bb * 1024 + row)) * 1024 + hh * 64;
    #pragma unroll
    for (int d = 0; d < 64; d += 4) {
        float4 ov;
        ov.x = o[d] * inv; ov.y = o[d+1] * inv; ov.z = o[d+2] * inv; ov.w = o[d+3] * inv;
        *(float4*)(op + d) = ov;
    }
}

// =================================================================================
// LayerNorm (two-pass): gamma*(x-mean)/(std+eps)+beta
// =================================================================================
__global__ void __launch_bounds__(256) layernorm_k(
    const float* __restrict__ in, const float* __restrict__ gamma,
    const float* __restrict__ beta, float* __restrict__ out)
{
    __shared__ float red[256];
    const int row = blockIdx.x;
    const int tid = threadIdx.x;

    const float4 v = ((const float4*)(in + (size_t)row * 1024))[tid];
    float s = v.x + v.y + v.z + v.w;
    red[tid] = s;
    __syncthreads();
    #pragma unroll
    for (int off = 128; off > 0; off >>= 1) {
        if (tid < off) red[tid] += red[tid + off];
        __syncthreads();
    }
    const float mean = red[0] * (1.f / 1024.f);
    __syncthreads();

    const float d0 = v.x - mean, d1 = v.y - mean, d2 = v.z - mean, d3 = v.w - mean;
    s = d0 * d0 + d1 * d1 + d2 * d2 + d3 * d3;
    red[tid] = s;
    __syncthreads();
    #pragma unroll
    for (int off = 128; off > 0; off >>= 1) {
        if (tid < off) red[tid] += red[tid + off];
        __syncthreads();
    }
    const float var = red[0] * (1.f / 1024.f);
    const float inv = 1.f / (sqrtf(var) + LN_EPS);

    const float4 gv = ((const float4*)gamma)[tid];
    const float4 bv = ((const float4*)beta)[tid];
    float4 ov;
    ov.x = gv.x * d0 * inv + bv.x;
    ov.y = gv.y * d1 * inv + bv.y;
    ov.z = gv.z * d2 * inv + bv.z;
    ov.w = gv.w * d3 * inv + bv.w;
    ((float4*)(out + (size_t)row * 1024))[tid] = ov;
}

// =================================================================================
// Launch
// =================================================================================
static float* sym_addr(const void* symbol)
{
    void* p = nullptr;
    cudaGetSymbolAddress(&p, symbol);
    return (float*)p;
}

extern "C" void kernel_launch(void* const* d_in, const int* in_sizes, int n_in,
                              void* d_out, int out_size)
{
    const float* x     = (const float*)d_in[0];
    const float* wq    = (const float*)d_in[1];
    const float* bq    = (const float*)d_in[2];
    const float* wk    = (const float*)d_in[3];
    const float* bk    = (const float*)d_in[4];
    const float* wv    = (const float*)d_in[5];
    const float* bv    = (const float*)d_in[6];
    const float* wo_w  = (const float*)d_in[7];
    const float* wo_b  = (const float*)d_in[8];
    const float* g1    = (const float*)d_in[9];
    const float* b1    = (const float*)d_in[10];
    const float* ff1_w = (const float*)d_in[11];
    const float* ff1_b = (const float*)d_in[12];
    const float* ff2_w = (const float*)d_in[13];
    const float* ff2_b = (const float*)d_in[14];
    const float* g2    = (const float*)d_in[15];
    const float* b2    = (const float*)d_in[16];

    float* qkv  = sym_addr(g_qkv);
    float* attn = sym_addr(g_attn);
    float* tmp  = sym_addr(g_tmp);
    float* h    = sym_addr(g_h);
    float* ff   = sym_addr(g_ff);
    float* wqkv = sym_addr(g_wqkv);
    float* bqkv = sym_addr(g_bqkv);

    cudaFuncSetAttribute(gemm_mma, cudaFuncAttributeMaxDynamicSharedMemorySize, SMEM_TOT);

    // 0) pack QKV weights/bias
    pack_qkv_k<<<(DM * 3 * DM) / 256, 256>>>(wq, wk, wv, bq, bk, bv);

    // 1) fused QKV projection: [4096,1024]@[1024,3072]
    gemm_mma<<<dim3(24, 32), 256, SMEM_TOT>>>(x, wqkv, bqkv, nullptr, qkv, ROWS, 3 * DM, DM, 0);

    // 2) attention
    attn_k<<<dim3(SEQ / 128, B_SZ * NH), 128>>>();

    // 3) output projection + residual(x)
    gemm_mma<<<dim3(8, 32), 256, SMEM_TOT>>>(attn, wo_w, wo_b, x, tmp, ROWS, DM, DM, 0);

    // 4) LayerNorm 1
    layernorm_k<<<ROWS, 256>>>(tmp, g1, b1, h);

    // 5) FF1 + ReLU
    gemm_mma<<<dim3(16, 32), 256, SMEM_TOT>>>(h, ff1_w, ff1_b, nullptr, ff, ROWS, DFF, DM, 1);

    // 6) FF2 + residual(h)
    gemm_mma<<<dim3(8, 32), 256, SMEM_TOT>>>(ff, ff2_w, ff2_b, h, tmp, ROWS, DM, DFF, 0);

    // 7) LayerNorm 2 -> output
    layernorm_k<<<ROWS, 256>>>(tmp, g2, b2, (float*)d_out);
}

// round 5
// speedup vs baseline: 2.3478x; 1.4087x over previous
#include <cuda_runtime.h>
#include <cuda_bf16.h>
#include <math.h>
#include <cstdint>

#define B_SZ   4
#define SEQ    1024
#define DM     1024
#define NH     16
#define DFF    2048
#define ROWS   (B_SZ*SEQ)        // 4096
#define LN_EPS 1e-5f

// GEMM smem tile geometry (per buffer): 4 bf16 tiles, 128 rows x 40 bf16 (80B stride)
#define ROWB      80
#define TILE_B    (128*ROWB)
#define OFF_AHI   0
#define OFF_ALO   (TILE_B)
#define OFF_BHI   (2*TILE_B)
#define OFF_BLO   (3*TILE_B)
#define BUF_B     (4*TILE_B)     // 40960
#define SMEM_TOT  (2*BUF_B)      // 81920

// Attention smem geometry: KV tile = 64 keys x 64 dims bf16, 144B row stride
#define AROWB     144
#define ATILE     (64*AROWB)     // 9216
#define AKHI      0
#define AKLO      (ATILE)
#define AVHI      (2*ATILE)
#define AVLO      (3*ATILE)
#define ABUF      (4*ATILE)      // 36864
#define ASMEM     (2*ABUF)       // 73728

// ---------------- scratch (device globals; no allocation allowed) ----------------
__device__ float g_qkv[ROWS*3*DM];        // [B*S, 3072]
__device__ float g_attn[ROWS*DM];
__device__ float g_tmp[ROWS*DM];
__device__ float g_h[ROWS*DM];
__device__ float g_ff[ROWS*DFF];
__device__ float g_wqkv[DM*3*DM];
__device__ float g_bqkv[3*DM];

// =================================================================================
// helpers
// =================================================================================
__device__ __forceinline__ uint32_t smem_u32(const void* p) {
    uint32_t a;
    asm("{ .reg .u64 t; cvta.to.shared.u64 t, %1; cvt.u32.u64 %0, t; }" : "=r"(a) : "l"(p));
    return a;
}

__device__ __forceinline__ void ldsm4(uint32_t* r, uint32_t addr) {
    asm volatile("ldmatrix.sync.aligned.m8n8.x4.shared.b16 {%0,%1,%2,%3}, [%4];"
                 : "=r"(r[0]), "=r"(r[1]), "=r"(r[2]), "=r"(r[3]) : "r"(addr));
}

__device__ __forceinline__ void ldsm4t(uint32_t* r, uint32_t addr) {
    asm volatile("ldmatrix.sync.aligned.m8n8.x4.trans.shared.b16 {%0,%1,%2,%3}, [%4];"
                 : "=r"(r[0]), "=r"(r[1]), "=r"(r[2]), "=r"(r[3]) : "r"(addr));
}

__device__ __forceinline__ void mma_bf16(float* d, const uint32_t* a, uint32_t b0, uint32_t b1) {
    asm volatile("mma.sync.aligned.m16n8k16.row.col.f32.bf16.bf16.f32 "
                 "{%0,%1,%2,%3}, {%4,%5,%6,%7}, {%8,%9}, {%0,%1,%2,%3};"
                 : "+f"(d[0]), "+f"(d[1]), "+f"(d[2]), "+f"(d[3])
                 : "r"(a[0]), "r"(a[1]), "r"(a[2]), "r"(a[3]), "r"(b0), "r"(b1));
}

__device__ __forceinline__ void split2(float a, float b, uint32_t& hi, uint32_t& lo) {
    __nv_bfloat16 ah = __float2bfloat16(a);
    __nv_bfloat16 bh = __float2bfloat16(b);
    __nv_bfloat16 al = __float2bfloat16(a - __bfloat162float(ah));
    __nv_bfloat16 bl = __float2bfloat16(b - __bfloat162float(bh));
    __nv_bfloat162 h2; h2.x = ah; h2.y = bh;
    __nv_bfloat162 l2; l2.x = al; l2.y = bl;
    hi = *reinterpret_cast<uint32_t*>(&h2);
    lo = *reinterpret_cast<uint32_t*>(&l2);
}

__device__ __forceinline__ uint32_t packbf(float a, float b) {
    __nv_bfloat162 t; t.x = __float2bfloat16(a); t.y = __float2bfloat16(b);
    return *reinterpret_cast<uint32_t*>(&t);
}

// =================================================================================
// Pack QKV weights into [1024 K, 3072 N] and bias into [3072]
// =================================================================================
__global__ void __launch_bounds__(256) pack_qkv_k(
    const float* __restrict__ wq, const float* __restrict__ wk, const float* __restrict__ wv,
    const float* __restrict__ bq, const float* __restrict__ bk, const float* __restrict__ bv)
{
    const int idx = blockIdx.x * 256 + threadIdx.x;
    const int n = idx % 3072;
    const int k = idx / 3072;
    const int t = n >> 10;
    const int rem = n & 1023;
    const float* w = (t == 0) ? wq : (t == 1) ? wk : wv;
    g_wqkv[idx] = w[(((rem >> 6) << 10) + k) * 64 + (rem & 63)];
    if (idx < 3072) {
        const float* bp = (t == 0) ? bq : (t == 1) ? bk : bv;
        g_bqkv[idx] = bp[rem];
    }
}

// =================================================================================
// mma.sync bf16x2-split GEMM: C = A@B + bias (+res) (relu opt)
// Pass-major MMA ordering for ILP (16 independent MMAs between acc revisits).
// =================================================================================
__global__ void __launch_bounds__(256) gemm_mma(
    const float* __restrict__ A, const float* __restrict__ Bm,
    const float* __restrict__ bias, const float* __restrict__ res,
    float* __restrict__ C, int M, int N, int K, int relu)
{
    extern __shared__ __align__(128) char sm[];
    const uint32_t sbase = smem_u32(sm);

    const int tid  = threadIdx.x;
    const int wid  = tid >> 5;
    const int lane = tid & 31;
    const int bm = blockIdx.y * 128;
    const int bn = blockIdx.x * 128;
    const int warp_m = wid & 3;
    const int warp_n = wid >> 2;

    const int ar  = tid >> 1;
    const int ak  = (tid & 1) * 16;
    const int bnl = tid & 127;
    const int bkl = (tid >> 7) * 16;

    const float* Ap = A + (size_t)(bm + ar) * K + ak;
    const float* Bp = Bm + (size_t)bkl * N + bn + bnl;

    float acc[2][8][4];
    #pragma unroll
    for (int i = 0; i < 2; i++)
        #pragma unroll
        for (int j = 0; j < 8; j++)
            #pragma unroll
            for (int q = 0; q < 4; q++) acc[i][j][q] = 0.f;

    float a_pre[16], b_pre[16];
    const int NCH = K >> 5;

    #pragma unroll
    for (int i = 0; i < 4; i++)
        *(float4*)&a_pre[4 * i] = *(const float4*)(Ap + 4 * i);
    #pragma unroll
    for (int i = 0; i < 16; i++)
        b_pre[i] = Bp[(size_t)i * N];

    for (int c = 0; c < NCH; c++) {
        const uint32_t buf = sbase + (uint32_t)(c & 1) * BUF_B;
        char* bufc = sm + (c & 1) * BUF_B;

        #pragma unroll
        for (int i = 0; i < 4; i++) {
            uint32_t h01, l01, h23, l23;
            split2(a_pre[4 * i],     a_pre[4 * i + 1], h01, l01);
            split2(a_pre[4 * i + 2], a_pre[4 * i + 3], h23, l23);
            const uint32_t off = (uint32_t)(ar * ROWB + (ak + 4 * i) * 2);
            *(uint2*)(bufc + OFF_AHI + off) = make_uint2(h01, h23);
            *(uint2*)(bufc + OFF_ALO + off) = make_uint2(l01, l23);
        }
        #pragma unroll
        for (int g = 0; g < 4; g++) {
            uint32_t h01, l01, h23, l23;
            split2(b_pre[4 * g],     b_pre[4 * g + 1], h01, l01);
            split2(b_pre[4 * g + 2], b_pre[4 * g + 3], h23, l23);
            const uint32_t off = (uint32_t)(bnl * ROWB + (bkl + 4 * g) * 2);
            *(uint2*)(bufc + OFF_BHI + off) = make_uint2(h01, h23);
            *(uint2*)(bufc + OFF_BLO + off) = make_uint2(l01, l23);
        }
        __syncthreads();

        if (c + 1 < NCH) {
            const int k0 = (c + 1) * 32;
            #pragma unroll
            for (int i = 0; i < 4; i++)
                *(float4*)&a_pre[4 * i] = *(const float4*)(Ap + k0 + 4 * i);
            #pragma unroll
            for (int i = 0; i < 16; i++)
                b_pre[i] = Bp[(size_t)(k0 + i) * N];
        }

        #pragma unroll
        for (int ks = 0; ks < 2; ks++) {
            uint32_t a_hi[2][4], a_lo[2][4];
            {
                const int arow = warp_m * 32 + (lane & 15);
                const int acol = ks * 16 + (lane >> 4) * 8;
                #pragma unroll
                for (int im = 0; im < 2; im++) {
                    const uint32_t ad = buf + (uint32_t)((arow + im * 16) * ROWB + acol * 2);
                    ldsm4(a_hi[im], ad + OFF_AHI);
                    ldsm4(a_lo[im], ad + OFF_ALO);
                }
            }
            uint32_t b_hi[4][4], b_lo[4][4];
            {
                const int nrow = warp_n * 64 + ((lane >> 4) << 3) + (lane & 7);
                const int bcol = ks * 16 + ((lane >> 3) & 1) * 8;
                #pragma unroll
                for (int jb = 0; jb < 4; jb++) {
                    const uint32_t bd = buf + (uint32_t)((nrow + jb * 16) * ROWB + bcol * 2);
                    ldsm4(b_hi[jb], bd + OFF_BHI);
                    ldsm4(b_lo[jb], bd + OFF_BLO);
                }
            }
            // pass-major: 16 independent MMAs per pass
            #pragma unroll
            for (int im = 0; im < 2; im++)
                #pragma unroll
                for (int jn = 0; jn < 8; jn++) {
                    const int jb = jn >> 1, sl = (jn & 1) * 2;
                    mma_bf16(acc[im][jn], a_hi[im], b_hi[jb][sl], b_hi[jb][sl + 1]);
                }
            #pragma unroll
            for (int im = 0; im < 2; im++)
                #pragma unroll
                for (int jn = 0; jn < 8; jn++) {
                    const int jb = jn >> 1, sl = (jn & 1) * 2;
                    mma_bf16(acc[im][jn], a_hi[im], b_lo[jb][sl], b_lo[jb][sl + 1]);
                }
            #pragma unroll
            for (int im = 0; im < 2; im++)
                #pragma unroll
                for (int jn = 0; jn < 8; jn++) {
                    const int jb = jn >> 1, sl = (jn & 1) * 2;
                    mma_bf16(acc[im][jn], a_lo[im], b_hi[jb][sl], b_hi[jb][sl + 1]);
                }
        }
        __syncthreads();
    }

    const int row0 = bm + warp_m * 32 + (lane >> 2);
    const int col0 = bn + warp_n * 64 + (lane & 3) * 2;
    #pragma unroll
    for (int im = 0; im < 2; im++) {
        #pragma unroll
        for (int half = 0; half < 2; half++) {
            const int r = row0 + im * 16 + half * 8;
            float* cp = C + (size_t)r * N;
            const float* rp = res ? res + (size_t)r * N : nullptr;
            #pragma unroll
            for (int jn = 0; jn < 8; jn++) {
                const int cc = col0 + jn * 8;
                float2 o;
                o.x = acc[im][jn][2 * half]     + bias[cc];
                o.y = acc[im][jn][2 * half + 1] + bias[cc + 1];
                if (rp) {
                    const float2 rv = *(const float2*)(rp + cc);
                    o.x += rv.x; o.y += rv.y;
                }
                if (relu) { o.x = fmaxf(o.x, 0.f); o.y = fmaxf(o.y, 0.f); }
                *(float2*)(cp + cc) = o;
            }
        }
    }
}

// =================================================================================
// Tensor-core flash attention. grid (S/128, B*H), 256 threads (8 warps x 16 rows).
// QK^T: bf16x2 3-pass split. P·V: Phi x (Vhi + Vlo).
// =================================================================================
__global__ void __launch_bounds__(256) attn_mma_k()
{
    extern __shared__ __align__(128) char asmem[];
    const uint32_t sbase = smem_u32(asmem);
    const int tid  = threadIdx.x;
    const int wid  = tid >> 5;
    const int lane = tid & 31;
    const int bhid = blockIdx.y;
    const int bb = bhid >> 4, hh = bhid & 15;
    const int qbase = blockIdx.x * 128;

    const float* base = g_qkv + (size_t)(bb * 1024) * 3072;

    // ---- stage Q (scaled by 1/8) into smem fp32 [128][68] ----
    float* Qf = (float*)asmem;
    for (int i = tid; i < 128 * 64; i += 256) {
        const int r = i >> 6, c = i & 63;
        Qf[r * 68 + c] = base[(size_t)(qbase + r) * 3072 + hh * 64 + c] * 0.125f;
    }
    __syncthreads();

    // gather Q a-frags (hi/lo), 4 k16 steps
    uint32_t qhi[4][4], qlo[4][4];
    {
        const int r1 = wid * 16 + (lane >> 2);
        const int c0 = (lane & 3) * 2;
        #pragma unroll
        for (int t = 0; t < 4; t++)
            #pragma unroll
            for (int q = 0; q < 4; q++) {
                const int rr = r1 + (q & 1) * 8;
                const int cc = t * 16 + c0 + (q >> 1) * 8;
                split2(Qf[rr * 68 + cc], Qf[rr * 68 + cc + 1], qhi[t][q], qlo[t][q]);
            }
    }
    __syncthreads();   // Q consumed; smem now free for KV buffers

    const float* Kp = base + 1024 + hh * 64;
    const float* Vp = base + 2048 + hh * 64;
    const int lkey = tid >> 2;            // 0..63
    const int ldim = (tid & 3) * 16;

    float oacc[8][4];
    #pragma unroll
    for (int j = 0; j < 8; j++)
        #pragma unroll
        for (int q = 0; q < 4; q++) oacc[j][q] = 0.f;
    float m0 = -1e30f, m1 = -1e30f, l0 = 0.f, l1 = 0.f;

    float kreg[16], vreg[16];
    // prologue: LDG tile 0
    #pragma unroll
    for (int i = 0; i < 4; i++) {
        *(float4*)&kreg[4 * i] = *(const float4*)(Kp + (size_t)lkey * 3072 + ldim + 4 * i);
        *(float4*)&vreg[4 * i] = *(const float4*)(Vp + (size_t)lkey * 3072 + ldim + 4 * i);
    }

    for (int t = 0; t < 16; t++) {
        char* bufc = asmem + (t & 1) * ABUF;
        const uint32_t bufu = sbase + (uint32_t)(t & 1) * ABUF;

        // ---- STS tile t (split to hi/lo bf16) ----
        #pragma unroll
        for (int i = 0; i < 4; i++) {
            uint32_t h01, l01, h23, l23;
            const uint32_t off = (uint32_t)(lkey * AROWB + (ldim + 4 * i) * 2);
            split2(kreg[4 * i], kreg[4 * i + 1], h01, l01);
            split2(kreg[4 * i + 2], kreg[4 * i + 3], h23, l23);
            *(uint2*)(bufc + AKHI + off) = make_uint2(h01, h23);
            *(uint2*)(bufc + AKLO + off) = make_uint2(l01, l23);
            split2(vreg[4 * i], vreg[4 * i + 1], h01, l01);
            split2(vreg[4 * i + 2], vreg[4 * i + 3], h23, l23);
            *(uint2*)(bufc + AVHI + off) = make_uint2(h01, h23);
            *(uint2*)(bufc + AVLO + off) = make_uint2(l01, l23);
        }
        __syncthreads();

        // ---- LDG tile t+1 ----
        if (t + 1 < 16) {
            const size_t kr = (size_t)((t + 1) * 64 + lkey) * 3072 + ldim;
            #pragma unroll
            for (int i = 0; i < 4; i++) {
                *(float4*)&kreg[4 * i] = *(const float4*)(Kp + kr + 4 * i);
                *(float4*)&vreg[4 * i] = *(const float4*)(Vp + kr + 4 * i);
            }
        }

        // ---- QK^T scores: 16 rows x 64 keys per warp ----
        float s[8][4];
        #pragma unroll
        for (int j = 0; j < 8; j++)
            #pragma unroll
            for (int q = 0; q < 4; q++) s[j][q] = 0.f;

        #pragma unroll
        for (int ks = 0; ks < 4; ks++) {
            uint32_t kh[4][4], kl[4][4];
            const int nro = ((lane >> 4) << 3) + (lane & 7);
            const int kco = ks * 16 + ((lane >> 3) & 1) * 8;
            #pragma unroll
            for (int g = 0; g < 4; g++) {
                const uint32_t ad = bufu + (uint32_t)((g * 16 + nro) * AROWB + kco * 2);
                ldsm4(kh[g], ad + AKHI);
                ldsm4(kl[g], ad + AKLO);
            }
            #pragma unroll
            for (int g = 0; g < 4; g++) {
                mma_bf16(s[2 * g],     qhi[ks], kh[g][0], kh[g][1]);
                mma_bf16(s[2 * g + 1], qhi[ks], kh[g][2], kh[g][3]);
            }
            #pragma unroll
            for (int g = 0; g < 4; g++) {
                mma_bf16(s[2 * g],     qhi[ks], kl[g][0], kl[g][1]);
                mma_bf16(s[2 * g + 1], qhi[ks], kl[g][2], kl[g][3]);
            }
            #pragma unroll
            for (int g = 0; g < 4; g++) {
                mma_bf16(s[2 * g],     qlo[ks], kh[g][0], kh[g][1]);
                mma_bf16(s[2 * g + 1], qlo[ks], kh[g][2], kh[g][3]);
            }
        }

        // ---- online softmax ----
        float mx0 = s[0][0], mx1 = s[0][2];
        #pragma unroll
        for (int j = 0; j < 8; j++) {
            mx0 = fmaxf(mx0, fmaxf(s[j][0], s[j][1]));
            mx1 = fmaxf(mx1, fmaxf(s[j][2], s[j][3]));
        }
        mx0 = fmaxf(mx0, __shfl_xor_sync(0xFFFFFFFF, mx0, 1));
        mx0 = fmaxf(mx0, __shfl_xor_sync(0xFFFFFFFF, mx0, 2));
        mx1 = fmaxf(mx1, __shfl_xor_sync(0xFFFFFFFF, mx1, 1));
        mx1 = fmaxf(mx1, __shfl_xor_sync(0xFFFFFFFF, mx1, 2));
        const float nm0 = fmaxf(m0, mx0), nm1 = fmaxf(m1, mx1);
        const float sc0 = __expf(m0 - nm0), sc1 = __expf(m1 - nm1);
        m0 = nm0; m1 = nm1;
        l0 *= sc0; l1 *= sc1;
        #pragma unroll
        for (int j = 0; j < 8; j++) {
            oacc[j][0] *= sc0; oacc[j][1] *= sc0;
            oacc[j][2] *= sc1; oacc[j][3] *= sc1;
        }

        uint32_t aP[4][4];
        #pragma unroll
        for (int j = 0; j < 8; j++) {
            const float p0 = __expf(s[j][0] - m0);
            const float p1 = __expf(s[j][1] - m0);
            const float p2 = __expf(s[j][2] - m1);
            const float p3 = __expf(s[j][3] - m1);
            l0 += p0 + p1;
            l1 += p2 + p3;
            const int kt = j >> 1;
            if ((j & 1) == 0) { aP[kt][0] = packbf(p0, p1); aP[kt][1] = packbf(p2, p3); }
            else              { aP[kt][2] = packbf(p0, p1); aP[kt][3] = packbf(p2, p3); }
        }

        // ---- P·V ----
        #pragma unroll
        for (int ks = 0; ks < 4; ks++) {
            uint32_t vh[4][4], vl[4][4];
            const int kro = ks * 16 + ((lane >> 3) & 1) * 8 + (lane & 7);
            const int dco = ((lane >> 4) & 1) * 8;
            #pragma unroll
            for (int g = 0; g < 4; g++) {
                const uint32_t ad = bufu + (uint32_t)(kro * AROWB + (g * 16 + dco) * 2);
                ldsm4t(vh[g], ad + AVHI);
                ldsm4t(vl[g], ad + AVLO);
            }
            #pragma unroll
            for (int g = 0; g < 4; g++) {
                mma_bf16(oacc[2 * g],     aP[ks], vh[g][0], vh[g][1]);
                mma_bf16(oacc[2 * g + 1], aP[ks], vh[g][2], vh[g][3]);
            }
            #pragma unroll
            for (int g = 0; g < 4; g++) {
                mma_bf16(oacc[2 * g],     aP[ks], vl[g][0], vl[g][1]);
                mma_bf16(oacc[2 * g + 1], aP[ks], vl[g][2], vl[g][3]);
            }
        }
        __syncthreads();
    }

    // ---- finalize ----
    l0 += __shfl_xor_sync(0xFFFFFFFF, l0, 1);
    l0 += __shfl_xor_sync(0xFFFFFFFF, l0, 2);
    l1 += __shfl_xor_sync(0xFFFFFFFF, l1, 1);
    l1 += __shfl_xor_sync(0xFFFFFFFF, l1, 2);
    const float inv0 = 1.f / l0, inv1 = 1.f / l1;

    const int r1 = qbase + wid * 16 + (lane >> 2);
    const int c0 = (lane & 3) * 2;
    float* o1 = g_attn + ((size_t)(bb * 1024 + r1)) * 1024 + hh * 64;
    float* o2 = o1 + 8 * 1024;
    #pragma unroll
    for (int j = 0; j < 8; j++) {
        const int cc = j * 8 + c0;
        *(float2*)(o1 + cc) = make_float2(oacc[j][0] * inv0, oacc[j][1] * inv0);
        *(float2*)(o2 + cc) = make_float2(oacc[j][2] * inv1, oacc[j][3] * inv1);
    }
}

// =================================================================================
// LayerNorm (two-pass): gamma*(x-mean)/(std+eps)+beta
// =================================================================================
__global__ void __launch_bounds__(256) layernorm_k(
    const float* __restrict__ in, const float* __restrict__ gamma,
    const float* __restrict__ beta, float* __restrict__ out)
{
    __shared__ float red[256];
    const int row = blockIdx.x;
    const int tid = threadIdx.x;

    const float4 v = ((const float4*)(in + (size_t)row * 1024))[tid];
    float s = v.x + v.y + v.z + v.w;
    red[tid] = s;
    __syncthreads();
    #pragma unroll
    for (int off = 128; off > 0; off >>= 1) {
        if (tid < off) red[tid] += red[tid + off];
        __syncthreads();
    }
    const float mean = red[0] * (1.f / 1024.f);
    __syncthreads();

    const float d0 = v.x - mean, d1 = v.y - mean, d2 = v.z - mean, d3 = v.w - mean;
    s = d0 * d0 + d1 * d1 + d2 * d2 + d3 * d3;
    red[tid] = s;
    __syncthreads();
    #pragma unroll
    for (int off = 128; off > 0; off >>= 1) {
        if (tid < off) red[tid] += red[tid + off];
        __syncthreads();
    }
    const float var = red[0] * (1.f / 1024.f);
    const float inv = 1.f / (sqrtf(var) + LN_EPS);

    const float4 gv = ((const float4*)gamma)[tid];
    const float4 bv = ((const float4*)beta)[tid];
    float4 ov;
    ov.x = gv.x * d0 * inv + bv.x;
    ov.y = gv.y * d1 * inv + bv.y;
    ov.z = gv.z * d2 * inv + bv.z;
    ov.w = gv.w * d3 * inv + bv.w;
    ((float4*)(out + (size_t)row * 1024))[tid] = ov;
}

// =================================================================================
// Launch
// =================================================================================
static float* sym_addr(const void* symbol)
{
    void* p = nullptr;
    cudaGetSymbolAddress(&p, symbol);
    return (float*)p;
}

extern "C" void kernel_launch(void* const* d_in, const int* in_sizes, int n_in,
                              void* d_out, int out_size)
{
    const float* x     = (const float*)d_in[0];
    const float* wq    = (const float*)d_in[1];
    const float* bq    = (const float*)d_in[2];
    const float* wk    = (const float*)d_in[3];
    const float* bk    = (const float*)d_in[4];
    const float* wv    = (const float*)d_in[5];
    const float* bv    = (const float*)d_in[6];
    const float* wo_w  = (const float*)d_in[7];
    const float* wo_b  = (const float*)d_in[8];
    const float* g1    = (const float*)d_in[9];
    const float* b1    = (const float*)d_in[10];
    const float* ff1_w = (const float*)d_in[11];
    const float* ff1_b = (const float*)d_in[12];
    const float* ff2_w = (const float*)d_in[13];
    const float* ff2_b = (const float*)d_in[14];
    const float* g2    = (const float*)d_in[15];
    const float* b2    = (const float*)d_in[16];

    float* qkv  = sym_addr(g_qkv);
    float* attn = sym_addr(g_attn);
    float* tmp  = sym_addr(g_tmp);
    float* h    = sym_addr(g_h);
    float* ff   = sym_addr(g_ff);
    float* wqkv = sym_addr(g_wqkv);
    float* bqkv = sym_addr(g_bqkv);

    cudaFuncSetAttribute(gemm_mma, cudaFuncAttributeMaxDynamicSharedMemorySize, SMEM_TOT);
    cudaFuncSetAttribute(attn_mma_k, cudaFuncAttributeMaxDynamicSharedMemorySize, ASMEM);

    // 0) pack QKV weights/bias
    pack_qkv_k<<<(DM * 3 * DM) / 256, 256>>>(wq, wk, wv, bq, bk, bv);

    // 1) fused QKV projection
    gemm_mma<<<dim3(24, 32), 256, SMEM_TOT>>>(x, wqkv, bqkv, nullptr, qkv, ROWS, 3 * DM, DM, 0);

    // 2) attention (tensor cores)
    attn_mma_k<<<dim3(SEQ / 128, B_SZ * NH), 256, ASMEM>>>();

    // 3) output projection + residual(x)
    gemm_mma<<<dim3(8, 32), 256, SMEM_TOT>>>(attn, wo_w, wo_b, x, tmp, ROWS, DM, DM, 0);

    // 4) LayerNorm 1
    layernorm_k<<<ROWS, 256>>>(tmp, g1, b1, h);

    // 5) FF1 + ReLU
    gemm_mma<<<dim3(16, 32), 256, SMEM_TOT>>>(h, ff1_w, ff1_b, nullptr, ff, ROWS, DFF, DM, 1);

    // 6) FF2 + residual(h)
    gemm_mma<<<dim3(8, 32), 256, SMEM_TOT>>>(ff, ff2_w, ff2_b, h, tmp, ROWS, DM, DFF, 0);

    // 7) LayerNorm 2 -> output
    layernorm_k<<<ROWS, 256>>>(tmp, g2, b2, (float*)d_out);
}